// round 4
// baseline (speedup 1.0000x reference)
#include <cuda_runtime.h>
#include <cuda_bf16.h>
#include <cstdint>
#include <math.h>

#define BB 2
#define LL 2048
#define DM 1024
#define DI 2048
#define DS 16
#define DR 64
#define NXD 96          // DR + 2*DS
#define MM (BB*LL)      // 4096

// smem tile geometry: 128 rows x 32 bf16 cols, row stride 80B (conflict-free ldmatrix)
#define ROW_B   80
#define TILE_B  (128 * ROW_B)      // 10240
#define STAGE_B (4 * TILE_B)       // 40960 (Ah, Al, Bh, Bl)
#define SMEM_B  (2 * STAGE_B)      // 81920

// ---------------- fp32 scratch ----------------
__device__ float g_xz[(size_t)MM * (2*DI)];
__device__ float g_xc[(size_t)MM * DI];
__device__ float g_xdbl[(size_t)MM * NXD];
__device__ float g_delta[(size_t)MM * DI];

// ---------------- bf16 hi/lo operand buffers ----------------
__device__ __nv_bfloat16 g_x_hi [(size_t)MM * DM],     g_x_lo [(size_t)MM * DM];
__device__ __nv_bfloat16 g_w1_hi[(size_t)2*DI * DM],   g_w1_lo[(size_t)2*DI * DM];
__device__ __nv_bfloat16 g_wx_hi[(size_t)NXD * DI],    g_wx_lo[(size_t)NXD * DI];
__device__ __nv_bfloat16 g_wd_hi[(size_t)DI * DR],     g_wd_lo[(size_t)DI * DR];
__device__ __nv_bfloat16 g_wo_hi[(size_t)DM * DI],     g_wo_lo[(size_t)DM * DI];
__device__ __nv_bfloat16 g_wf_hi[(size_t)DM * DM],     g_wf_lo[(size_t)DM * DM];
__device__ __nv_bfloat16 g_xc_hi[(size_t)MM * DI],     g_xc_lo[(size_t)MM * DI];
__device__ __nv_bfloat16 g_xd_hi[(size_t)MM * NXD],    g_xd_lo[(size_t)MM * NXD];
__device__ __nv_bfloat16 g_y_hi [(size_t)MM * DI],     g_y_lo [(size_t)MM * DI];
__device__ __nv_bfloat16 g_o1_hi[(size_t)MM * DM],     g_o1_lo[(size_t)MM * DM];

// ---------------- helpers ----------------
__device__ __forceinline__ void mma_bf16(float* c, const uint32_t* a, const uint32_t* b) {
    asm volatile(
        "mma.sync.aligned.m16n8k16.row.col.f32.bf16.bf16.f32 "
        "{%0,%1,%2,%3}, {%4,%5,%6,%7}, {%8,%9}, {%0,%1,%2,%3};"
        : "+f"(c[0]), "+f"(c[1]), "+f"(c[2]), "+f"(c[3])
        : "r"(a[0]), "r"(a[1]), "r"(a[2]), "r"(a[3]), "r"(b[0]), "r"(b[1]));
}
__device__ __forceinline__ void ldsm_x4(uint32_t* r, uint32_t addr) {
    asm volatile("ldmatrix.sync.aligned.m8n8.x4.shared.b16 {%0,%1,%2,%3}, [%4];"
        : "=r"(r[0]), "=r"(r[1]), "=r"(r[2]), "=r"(r[3]) : "r"(addr));
}
__device__ __forceinline__ void cp16(uint32_t dst, const void* src, bool valid) {
    int sz = valid ? 16 : 0;
    asm volatile("cp.async.cg.shared.global [%0], [%1], 16, %2;"
        :: "r"(dst), "l"(src), "r"(sz));
}
__device__ __forceinline__ uint32_t pack_hi(float a, float b) {
    __nv_bfloat16 h0 = __float2bfloat16_rn(a), h1 = __float2bfloat16_rn(b);
    return (uint32_t)__bfloat16_as_ushort(h0) | ((uint32_t)__bfloat16_as_ushort(h1) << 16);
}
__device__ __forceinline__ uint32_t pack_lo(float a, float b) {
    __nv_bfloat16 h0 = __float2bfloat16_rn(a), h1 = __float2bfloat16_rn(b);
    float r0 = a - __bfloat162float(h0), r1 = b - __bfloat162float(h1);
    __nv_bfloat16 l0 = __float2bfloat16_rn(r0), l1 = __float2bfloat16_rn(r1);
    return (uint32_t)__bfloat16_as_ushort(l0) | ((uint32_t)__bfloat16_as_ushort(l1) << 16);
}

// ---------------- split fp32 -> bf16 hi/lo (vectorized) ----------------
__global__ __launch_bounds__(256)
void split4_kernel(const float4* __restrict__ src, uint2* __restrict__ hi,
                   uint2* __restrict__ lo, int n4)
{
    int i = blockIdx.x * blockDim.x + threadIdx.x;
    if (i >= n4) return;
    float4 v = src[i];
    hi[i] = make_uint2(pack_hi(v.x, v.y), pack_hi(v.z, v.w));
    lo[i] = make_uint2(pack_lo(v.x, v.y), pack_lo(v.z, v.w));
}

// ================= HMMA GEMM: C[M,N] = A[M,K] * B[N,K]^T, bf16 hi/lo operands =================
// CTA 128x128, BK=32, 8 warps (32x64 warptile), 2-stage cp.async pipeline.
template<int EPI, bool F32S, bool HLS>
__global__ __launch_bounds__(256, 2)
void hmma_gemm(const __nv_bfloat16* __restrict__ Ah, const __nv_bfloat16* __restrict__ Al, int lda,
               const __nv_bfloat16* __restrict__ Bh, const __nv_bfloat16* __restrict__ Bl, int ldb,
               float* __restrict__ C, __nv_bfloat16* __restrict__ Chi,
               __nv_bfloat16* __restrict__ Clo, int ldc,
               int N, int K, const float* __restrict__ bias)
{
    extern __shared__ char smem[];
    const uint32_t su = (uint32_t)__cvta_generic_to_shared(smem);

    const int tid  = threadIdx.x;
    const int wid  = tid >> 5;
    const int lane = tid & 31;
    const int bm = blockIdx.y * 128;
    const int bn = blockIdx.x * 128;
    const int warp_m = wid & 3;
    const int warp_n = wid >> 2;
    const int b_rows = min(128, N - bn);

    float acc[2][8][4];
    #pragma unroll
    for (int i = 0; i < 2; i++)
        #pragma unroll
        for (int j = 0; j < 8; j++)
            #pragma unroll
            for (int q = 0; q < 4; q++) acc[i][j][q] = 0.f;

    // staging: 512 16B-chunks per tile / 256 thr = 2 per thread per tile
    const int nch = K >> 5;

    auto issue_stage = [&](int stg, int k0) {
        const uint32_t sb = su + (uint32_t)(stg * STAGE_B);
        #pragma unroll
        for (int i = 0; i < 2; i++) {
            const int id  = tid + i * 256;
            const int row = id >> 2;
            const int ce  = (id & 3) << 3;                 // elem col 0,8,16,24
            const uint32_t doff = (uint32_t)(row * ROW_B + (id & 3) * 16);
            const size_t aoff = (size_t)(bm + row) * lda + k0 + ce;
            cp16(sb + doff,              Ah + aoff, true);
            cp16(sb + TILE_B + doff,     Al + aoff, true);
            const bool v = row < b_rows;
            const size_t boff = (size_t)(bn + (v ? row : 0)) * ldb + k0 + ce;
            cp16(sb + 2*TILE_B + doff,   Bh + boff, v);
            cp16(sb + 3*TILE_B + doff,   Bl + boff, v);
        }
        asm volatile("cp.async.commit_group;" ::: "memory");
    };

    issue_stage(0, 0);
    if (nch > 1) issue_stage(1, 32);

    for (int c = 0; c < nch; c++) {
        if (c + 1 < nch) asm volatile("cp.async.wait_group 1;" ::: "memory");
        else             asm volatile("cp.async.wait_group 0;" ::: "memory");
        __syncthreads();

        const uint32_t sb = su + (uint32_t)((c & 1) * STAGE_B);
        const uint32_t lrow = (uint32_t)(lane & 15);
        const uint32_t kofs = (uint32_t)(((lane >> 4) << 3) * 2);

        #pragma unroll
        for (int ks = 0; ks < 2; ks++) {
            const uint32_t kb = (uint32_t)(ks * 32) + kofs;   // byte offset in row
            uint32_t ah[2][4], al[2][4];
            #pragma unroll
            for (int mt = 0; mt < 2; mt++) {
                const uint32_t ro = (uint32_t)(warp_m * 32 + mt * 16 + lrow) * ROW_B + kb;
                ldsm_x4(ah[mt], sb + ro);
                ldsm_x4(al[mt], sb + TILE_B + ro);
            }
            #pragma unroll
            for (int p = 0; p < 4; p++) {
                const uint32_t bo = (uint32_t)(warp_n * 64 + p * 16 + lrow) * ROW_B + kb;
                uint32_t bh[4], bl[4];
                ldsm_x4(bh, sb + 2*TILE_B + bo);
                ldsm_x4(bl, sb + 3*TILE_B + bo);
                uint32_t be[2], bo2[2];
                be[0] = bh[0]; be[1] = bh[2];      // nt = 2p
                bo2[0] = bh[1]; bo2[1] = bh[3];    // nt = 2p+1
                uint32_t le[2], lo2[2];
                le[0] = bl[0]; le[1] = bl[2];
                lo2[0] = bl[1]; lo2[1] = bl[3];
                #pragma unroll
                for (int mt = 0; mt < 2; mt++) {
                    mma_bf16(acc[mt][2*p],   ah[mt], be);
                    mma_bf16(acc[mt][2*p],   ah[mt], le);
                    mma_bf16(acc[mt][2*p],   al[mt], be);
                    mma_bf16(acc[mt][2*p+1], ah[mt], bo2);
                    mma_bf16(acc[mt][2*p+1], ah[mt], lo2);
                    mma_bf16(acc[mt][2*p+1], al[mt], bo2);
                }
            }
        }
        __syncthreads();
        if (c + 2 < nch) issue_stage(c & 1, (c + 2) << 5);
    }

    // epilogue: lane l -> rows (l>>2, l>>2+8), cols 2*(l&3)+{0,1}
    #pragma unroll
    for (int mt = 0; mt < 2; mt++) {
        const int r0 = bm + warp_m * 32 + mt * 16 + (lane >> 2);
        #pragma unroll
        for (int nt = 0; nt < 8; nt++) {
            const int col = bn + warp_n * 64 + nt * 8 + ((lane & 3) << 1);
            if (col < N) {
                float v[4];
                #pragma unroll
                for (int q = 0; q < 4; q++) {
                    float val = acc[mt][nt][q];
                    if (EPI == 1) {
                        val += bias[col + (q & 1)];
                        val = fmaxf(val, 0.f) + log1pf(__expf(-fabsf(val)));
                    }
                    if (EPI == 2) {
                        val += bias[col + (q & 1)];
                        val = val / (1.f + __expf(-val));
                    }
                    v[q] = val;
                }
                if (F32S) {
                    *reinterpret_cast<float2*>(&C[(size_t)r0 * ldc + col]) = make_float2(v[0], v[1]);
                    *reinterpret_cast<float2*>(&C[(size_t)(r0 + 8) * ldc + col]) = make_float2(v[2], v[3]);
                }
                if (HLS) {
                    *reinterpret_cast<uint32_t*>(&Chi[(size_t)r0 * ldc + col])       = pack_hi(v[0], v[1]);
                    *reinterpret_cast<uint32_t*>(&Clo[(size_t)r0 * ldc + col])       = pack_lo(v[0], v[1]);
                    *reinterpret_cast<uint32_t*>(&Chi[(size_t)(r0 + 8) * ldc + col]) = pack_hi(v[2], v[3]);
                    *reinterpret_cast<uint32_t*>(&Clo[(size_t)(r0 + 8) * ldc + col]) = pack_lo(v[2], v[3]);
                }
            }
        }
    }
}

// ---------------- causal depthwise conv(4) + SiLU (writes f32 + hi/lo) ----------------
__global__ __launch_bounds__(256)
void conv_silu_kernel(const float* __restrict__ w, const float* __restrict__ bias)
{
    int idx = blockIdx.x * blockDim.x + threadIdx.x;
    if (idx >= MM * DI) return;
    int d = idx & (DI - 1);
    int m = idx >> 11;
    int l = m & (LL - 1);

    float acc = bias[d];
    const float w0 = w[d*4+0], w1 = w[d*4+1], w2 = w[d*4+2], w3 = w[d*4+3];
    const float* base = g_xz + (size_t)m * (2 * DI) + d;
    const ptrdiff_t rs = 2 * DI;
    if (l >= 3) acc = fmaf(base[-3 * rs], w0, acc);
    if (l >= 2) acc = fmaf(base[-2 * rs], w1, acc);
    if (l >= 1) acc = fmaf(base[-1 * rs], w2, acc);
    acc = fmaf(base[0], w3, acc);
    float sig = 1.f / (1.f + __expf(-acc));
    float v = acc * sig;
    g_xc[(size_t)m * DI + d] = v;
    __nv_bfloat16 h = __float2bfloat16_rn(v);
    g_xc_hi[(size_t)m * DI + d] = h;
    g_xc_lo[(size_t)m * DI + d] = __float2bfloat16_rn(v - __bfloat162float(h));
}

// ---------------- selective scan (writes y hi/lo) ----------------
__global__ __launch_bounds__(256)
void scan_kernel(const float* __restrict__ A_log, const float* __restrict__ Dvec)
{
    const int tid  = threadIdx.x;
    const int warp = tid >> 5;
    const int lane = tid & 31;
    const int n = lane & 15;
    const int b = blockIdx.x >> 7;
    const int d = ((blockIdx.x & 127) << 4) + (warp << 1) + (lane >> 4);

    const float A  = -__expf(A_log[d * DS + n]);
    const float Dd = Dvec[d];
    float h = 0.f;

    const float* pd = g_delta + (size_t)b * LL * DI + d;
    const float* pu = g_xc    + (size_t)b * LL * DI + d;
    const float* pz = g_xz    + (size_t)b * LL * (2 * DI) + DI + d;
    const float* pb = g_xdbl  + (size_t)b * LL * NXD + DR + n;
    size_t       oy = (size_t)b * LL * DI + d;

    #pragma unroll 2
    for (int t = 0; t < LL; t++) {
        const float delta = __ldg(pd);
        const float u     = __ldg(pu);
        const float Bn    = __ldg(pb);
        const float Cn    = __ldg(pb + DS);

        const float e = __expf(delta * A);
        h = fmaf(e, h, delta * u * Bn);

        float p = h * Cn;
        p += __shfl_xor_sync(0xffffffffu, p, 1);
        p += __shfl_xor_sync(0xffffffffu, p, 2);
        p += __shfl_xor_sync(0xffffffffu, p, 4);
        p += __shfl_xor_sync(0xffffffffu, p, 8);

        if (n == 0) {
            const float z = __ldg(pz);
            const float sig = 1.f / (1.f + __expf(-z));
            const float val = (p + Dd * u) * (z * sig);
            __nv_bfloat16 hh = __float2bfloat16_rn(val);
            g_y_hi[oy] = hh;
            g_y_lo[oy] = __float2bfloat16_rn(val - __bfloat162float(hh));
        }
        pd += DI; pu += DI; pz += 2 * DI; pb += NXD; oy += DI;
    }
}

// ---------------- launch ----------------
extern "C" void kernel_launch(void* const* d_in, const int* in_sizes, int n_in,
                              void* d_out, int out_size)
{
    const float* x         = (const float*)d_in[0];
    const float* in_proj_w = (const float*)d_in[1];
    const float* conv_w    = (const float*)d_in[2];
    const float* conv_b    = (const float*)d_in[3];
    const float* x_proj_w  = (const float*)d_in[4];
    const float* dt_proj_w = (const float*)d_in[5];
    const float* dt_proj_b = (const float*)d_in[6];
    const float* A_log     = (const float*)d_in[7];
    const float* Dv        = (const float*)d_in[8];
    const float* ssm_out_w = (const float*)d_in[9];
    const float* final_w   = (const float*)d_in[10];
    const float* final_b   = (const float*)d_in[11];
    float* out = (float*)d_out;

    float *p_xz, *p_xc, *p_xdbl, *p_delta;
    __nv_bfloat16 *x_hi, *x_lo, *w1_hi, *w1_lo, *wx_hi, *wx_lo, *wd_hi, *wd_lo;
    __nv_bfloat16 *wo_hi, *wo_lo, *wf_hi, *wf_lo, *xc_hi, *xc_lo, *xd_hi, *xd_lo;
    __nv_bfloat16 *y_hi, *y_lo, *o1_hi, *o1_lo;
    cudaGetSymbolAddress((void**)&p_xz, g_xz);       cudaGetSymbolAddress((void**)&p_xc, g_xc);
    cudaGetSymbolAddress((void**)&p_xdbl, g_xdbl);   cudaGetSymbolAddress((void**)&p_delta, g_delta);
    cudaGetSymbolAddress((void**)&x_hi, g_x_hi);     cudaGetSymbolAddress((void**)&x_lo, g_x_lo);
    cudaGetSymbolAddress((void**)&w1_hi, g_w1_hi);   cudaGetSymbolAddress((void**)&w1_lo, g_w1_lo);
    cudaGetSymbolAddress((void**)&wx_hi, g_wx_hi);   cudaGetSymbolAddress((void**)&wx_lo, g_wx_lo);
    cudaGetSymbolAddress((void**)&wd_hi, g_wd_hi);   cudaGetSymbolAddress((void**)&wd_lo, g_wd_lo);
    cudaGetSymbolAddress((void**)&wo_hi, g_wo_hi);   cudaGetSymbolAddress((void**)&wo_lo, g_wo_lo);
    cudaGetSymbolAddress((void**)&wf_hi, g_wf_hi);   cudaGetSymbolAddress((void**)&wf_lo, g_wf_lo);
    cudaGetSymbolAddress((void**)&xc_hi, g_xc_hi);   cudaGetSymbolAddress((void**)&xc_lo, g_xc_lo);
    cudaGetSymbolAddress((void**)&xd_hi, g_xd_hi);   cudaGetSymbolAddress((void**)&xd_lo, g_xd_lo);
    cudaGetSymbolAddress((void**)&y_hi, g_y_hi);     cudaGetSymbolAddress((void**)&y_lo, g_y_lo);
    cudaGetSymbolAddress((void**)&o1_hi, g_o1_hi);   cudaGetSymbolAddress((void**)&o1_lo, g_o1_lo);

    cudaFuncSetAttribute(hmma_gemm<0,true,false>,  cudaFuncAttributeMaxDynamicSharedMemorySize, SMEM_B);
    cudaFuncSetAttribute(hmma_gemm<0,true,true>,   cudaFuncAttributeMaxDynamicSharedMemorySize, SMEM_B);
    cudaFuncSetAttribute(hmma_gemm<1,true,false>,  cudaFuncAttributeMaxDynamicSharedMemorySize, SMEM_B);
    cudaFuncSetAttribute(hmma_gemm<0,false,true>,  cudaFuncAttributeMaxDynamicSharedMemorySize, SMEM_B);
    cudaFuncSetAttribute(hmma_gemm<2,true,false>,  cudaFuncAttributeMaxDynamicSharedMemorySize, SMEM_B);

    auto split = [&](const float* s, __nv_bfloat16* h, __nv_bfloat16* l, int n) {
        split4_kernel<<<(n/4 + 255)/256, 256>>>((const float4*)s, (uint2*)h, (uint2*)l, n/4);
    };
    // operand splits
    split(x,         x_hi,  x_lo,  MM * DM);
    split(in_proj_w, w1_hi, w1_lo, 2 * DI * DM);
    split(x_proj_w,  wx_hi, wx_lo, NXD * DI);
    split(dt_proj_w, wd_hi, wd_lo, DI * DR);
    split(ssm_out_w, wo_hi, wo_lo, DM * DI);
    split(final_w,   wf_hi, wf_lo, DM * DM);

    // 1) in_proj -> g_xz (f32)
    hmma_gemm<0,true,false><<<dim3(32,32), 256, SMEM_B>>>(
        x_hi, x_lo, DM, w1_hi, w1_lo, DM, p_xz, nullptr, nullptr, 2*DI, 2*DI, DM, nullptr);

    // 2) conv + SiLU -> xc f32 + hi/lo
    conv_silu_kernel<<<(MM * DI) / 256, 256>>>(conv_w, conv_b);

    // 3a) x_dbl -> f32 + hi/lo
    hmma_gemm<0,true,true><<<dim3(1,32), 256, SMEM_B>>>(
        xc_hi, xc_lo, DI, wx_hi, wx_lo, DI, p_xdbl, xd_hi, xd_lo, NXD, NXD, DI, nullptr);

    // 3b) delta = softplus(dt @ W^T + b) -> f32
    hmma_gemm<1,true,false><<<dim3(16,32), 256, SMEM_B>>>(
        xd_hi, xd_lo, NXD, wd_hi, wd_lo, DR, p_delta, nullptr, nullptr, DI, DI, DR, dt_proj_b);

    // 4) scan -> y hi/lo
    scan_kernel<<<256, 256>>>(A_log, Dv);

    // 5) out_proj -> o1 hi/lo
    hmma_gemm<0,false,true><<<dim3(8,32), 256, SMEM_B>>>(
        y_hi, y_lo, DI, wo_hi, wo_lo, DI, nullptr, o1_hi, o1_lo, DM, DM, DI, nullptr);

    // 6) final: silu(o1 @ final_w^T + b) -> out
    hmma_gemm<2,true,false><<<dim3(8,32), 256, SMEM_B>>>(
        o1_hi, o1_lo, DM, wf_hi, wf_lo, DM, out, nullptr, nullptr, DM, DM, DM, final_b);
}